// round 7
// baseline (speedup 1.0000x reference)
#include <cuda_runtime.h>
#include <cuda_bf16.h>
#include <math.h>
#include <stdint.h>

#define N_ROWS 4096
#define D_IN   2048
#define D_HID  8192
#define D_OUT  2048
#define RANK   8

// ---------------------------------------------------------------------------
// Static device scratch (aligned for cp.async 16B)
// ---------------------------------------------------------------------------
__device__ float g_u[RANK * D_IN];
__device__ __align__(128) int8_t g_xq1[(size_t)N_ROWS * D_IN];
__device__ __align__(128) int8_t g_xq0[(size_t)N_ROWS * D_IN];
__device__ float g_sxq[N_ROWS];
__device__ __align__(128) int8_t g_wt1[(size_t)D_HID * D_IN];   // W_random^T slices
__device__ __align__(128) int8_t g_wt0[(size_t)D_HID * D_IN];
__device__ float g_swt[D_HID];
__device__ __align__(128) int8_t g_wo1[(size_t)D_OUT * D_HID];  // W_out^T slices
__device__ __align__(128) int8_t g_wo0[(size_t)D_OUT * D_HID];
__device__ float g_swo[D_OUT];
__device__ __align__(128) float g_h[(size_t)N_ROWS * D_HID];    // gelu out fp32
__device__ __align__(128) int8_t g_h1[(size_t)N_ROWS * D_HID];
__device__ __align__(128) int8_t g_h0[(size_t)N_ROWS * D_HID];
__device__ float g_sh[N_ROWS];

// ---------------------------------------------------------------------------
// PTX helpers
// ---------------------------------------------------------------------------
__device__ __forceinline__ uint32_t smem_u32(const void* p) {
    uint32_t a;
    asm("{ .reg .u64 t; cvta.to.shared.u64 t, %1; cvt.u32.u64 %0, t; }" : "=r"(a) : "l"(p));
    return a;
}
__device__ __forceinline__ void cp16(uint32_t s, const void* g) {
    asm volatile("cp.async.cg.shared.global [%0], [%1], 16;" :: "r"(s), "l"(g));
}
#define CP_COMMIT() asm volatile("cp.async.commit_group;" ::: "memory")
#define CP_WAIT(n)  asm volatile("cp.async.wait_group %0;" :: "n"(n) : "memory")

#define LDSM4(r0, r1, r2, r3, addr) \
    asm volatile("ldmatrix.sync.aligned.m8n8.x4.shared.b16 {%0,%1,%2,%3}, [%4];" \
                 : "=r"(r0), "=r"(r1), "=r"(r2), "=r"(r3) : "r"(addr))

#define MMA_S8(c, a, b0, b1) \
    asm volatile("mma.sync.aligned.m16n8k32.row.col.s32.s8.s8.s32 " \
                 "{%0,%1,%2,%3},{%4,%5,%6,%7},{%8,%9},{%0,%1,%2,%3};" \
                 : "+r"((c)[0]), "+r"((c)[1]), "+r"((c)[2]), "+r"((c)[3]) \
                 : "r"((a)[0]), "r"((a)[1]), "r"((a)[2]), "r"((a)[3]), "r"(b0), "r"(b1))

// ---------------------------------------------------------------------------
// Block reductions (256 threads)
// ---------------------------------------------------------------------------
__device__ __forceinline__ float blockReduceSum256(float v, float* sred) {
    #pragma unroll
    for (int o = 16; o > 0; o >>= 1) v += __shfl_down_sync(0xffffffffu, v, o);
    const int lane = threadIdx.x & 31;
    const int warp = threadIdx.x >> 5;
    if (lane == 0) sred[warp] = v;
    __syncthreads();
    if (threadIdx.x == 0) {
        float r = sred[0];
        #pragma unroll
        for (int i = 1; i < 8; i++) r += sred[i];
        sred[0] = r;
    }
    __syncthreads();
    float r = sred[0];
    __syncthreads();
    return r;
}
__device__ __forceinline__ float blockReduceMax256(float v, float* sred) {
    #pragma unroll
    for (int o = 16; o > 0; o >>= 1) v = fmaxf(v, __shfl_down_sync(0xffffffffu, v, o));
    const int lane = threadIdx.x & 31;
    const int warp = threadIdx.x >> 5;
    if (lane == 0) sred[warp] = v;
    __syncthreads();
    if (threadIdx.x == 0) {
        float r = sred[0];
        #pragma unroll
        for (int i = 1; i < 8; i++) r = fmaxf(r, sred[i]);
        sred[0] = r;
    }
    __syncthreads();
    float r = sred[0];
    __syncthreads();
    return r;
}

// quantize helper: v -> (a1, a0) given inv = 127/max
__device__ __forceinline__ void quant2(float v, float inv, int8_t& q1, int8_t& q0) {
    float s = v * inv;                 // in [-127, 127]
    float a1 = rintf(s);
    float a0 = rintf((s - a1) * 254.0f);
    q1 = (int8_t)(int)a1;
    q0 = (int8_t)(int)a0;
}

// ---------------------------------------------------------------------------
// 1) Modified Gram-Schmidt (matches reference order and eps)
// ---------------------------------------------------------------------------
__global__ void gs_kernel(const float* __restrict__ hra_u, float* __restrict__ u_out) {
    __shared__ float cur[D_IN];
    __shared__ float sred[8];
    const int tid = threadIdx.x;

    for (int i = 0; i < RANK; i++) {
        for (int d = tid; d < D_IN; d += 256) cur[d] = hra_u[(size_t)d * RANK + i];
        __syncthreads();
        for (int j = 0; j < i; j++) {
            const float* uj = u_out + (size_t)j * D_IN;
            float local = 0.f;
            for (int d = tid; d < D_IN; d += 256) local += uj[d] * cur[d];
            float dot = blockReduceSum256(local, sred);
            for (int d = tid; d < D_IN; d += 256) cur[d] -= dot * uj[d];
            __syncthreads();
        }
        float local = 0.f;
        for (int d = tid; d < D_IN; d += 256) local += cur[d] * cur[d];
        float nrm2 = blockReduceSum256(local, sred);
        float inv = 1.0f / (sqrtf(nrm2) + 1e-6f);
        for (int d = tid; d < D_IN; d += 256) u_out[(size_t)i * D_IN + d] = cur[d] * inv;
        __syncthreads();
    }
}

// ---------------------------------------------------------------------------
// 2) x @ Q via Householder reflections; quantize row to int8 slices
// ---------------------------------------------------------------------------
__global__ void __launch_bounds__(256) hh_quant_kernel(const float* __restrict__ x,
                                                       const float* __restrict__ u,
                                                       int8_t* __restrict__ q1,
                                                       int8_t* __restrict__ q0,
                                                       float* __restrict__ sc) {
    __shared__ float sred[8];
    const int row = blockIdx.x;
    const int tid = threadIdx.x;
    const float* xr = x + (size_t)row * D_IN;

    float v[8];
    #pragma unroll
    for (int j = 0; j < 8; j++) v[j] = xr[tid + j * 256];

    for (int i = 0; i < RANK; i++) {
        const float* ui = u + (size_t)i * D_IN;
        float uu[8];
        #pragma unroll
        for (int j = 0; j < 8; j++) uu[j] = ui[tid + j * 256];
        float local = 0.f;
        #pragma unroll
        for (int j = 0; j < 8; j++) local += v[j] * uu[j];
        float dot = blockReduceSum256(local, sred);
        float s = 2.0f * dot;
        #pragma unroll
        for (int j = 0; j < 8; j++) v[j] -= s * uu[j];
    }

    float m = 0.f;
    #pragma unroll
    for (int j = 0; j < 8; j++) m = fmaxf(m, fabsf(v[j]));
    m = blockReduceMax256(m, sred);
    m = fmaxf(m, 1e-30f);
    const float inv = 127.0f / m;
    if (tid == 0) sc[row] = m / 127.0f;

    #pragma unroll
    for (int j = 0; j < 8; j++) {
        size_t o = (size_t)row * D_IN + tid + j * 256;
        int8_t a1, a0;
        quant2(v[j], inv, a1, a0);
        q1[o] = a1; q0[o] = a0;
    }
}

// ---------------------------------------------------------------------------
// 3) column max -> per-column scale (scale = max/127)
// ---------------------------------------------------------------------------
__global__ void __launch_bounds__(256) colmax_scale_kernel(const float* __restrict__ in,
                                                           int R, int C,
                                                           float* __restrict__ sc) {
    const int c = blockIdx.x * 256 + threadIdx.x;
    float m = 1e-30f;
    for (int r = 0; r < R; r++) m = fmaxf(m, fabsf(in[(size_t)r * C + c]));
    sc[c] = m / 127.0f;
}

// ---------------------------------------------------------------------------
// 4) transpose + int8 2-slice quantize: in[R,C] fp32 -> q[C,R] int8 x2
// ---------------------------------------------------------------------------
__global__ void __launch_bounds__(256) transpose_quant_kernel(
    const float* __restrict__ in, const float* __restrict__ sc,
    int8_t* __restrict__ q1, int8_t* __restrict__ q0, int R, int C) {
    __shared__ float tile[32][33];
    const int c0 = blockIdx.x * 32, r0 = blockIdx.y * 32;
    const int tx = threadIdx.x, ty = threadIdx.y;
    #pragma unroll
    for (int j = 0; j < 32; j += 8)
        tile[ty + j][tx] = in[(size_t)(r0 + ty + j) * C + c0 + tx];
    __syncthreads();
    #pragma unroll
    for (int j = 0; j < 32; j += 8) {
        const int orow = c0 + ty + j;
        const float inv = 1.0f / sc[orow];   // = 127/max
        float v = tile[tx][ty + j];
        int8_t a1, a0;
        quant2(v, inv, a1, a0);
        size_t o = (size_t)orow * R + r0 + tx;
        q1[o] = a1; q0[o] = a0;
    }
}

// ---------------------------------------------------------------------------
// 5) row-wise quantize h fp32 [rows, C] -> int8 slices + scale
// ---------------------------------------------------------------------------
__global__ void __launch_bounds__(256) quant_rows_kernel(const float* __restrict__ in,
                                                         int8_t* __restrict__ q1,
                                                         int8_t* __restrict__ q0,
                                                         float* __restrict__ sc, int C) {
    __shared__ float sred[8];
    const int row = blockIdx.x;
    const int tid = threadIdx.x;
    const float* src = in + (size_t)row * C;
    float m = 0.f;
    for (int i = tid; i < C; i += 256) m = fmaxf(m, fabsf(src[i]));
    m = blockReduceMax256(m, sred);
    m = fmaxf(m, 1e-30f);
    const float inv = 127.0f / m;
    if (tid == 0) sc[row] = m / 127.0f;
    for (int i = tid; i < C; i += 256) {
        int8_t a1, a0;
        quant2(src[i], inv, a1, a0);
        size_t o = (size_t)row * C + i;
        q1[o] = a1; q0[o] = a0;
    }
}

// ---------------------------------------------------------------------------
// 6) IMMA GEMM: C[M,N] = (sA sB) [P11 + (P10+P01)/254],  A,B int8 2-slice.
//    Block 128x128, 512 thr (16 warps 4x4, warp tile 32x32), BK=64 bytes,
//    2-stage cp.async, 80B-padded rows (conflict-free ldmatrix).
//    EPI 0: gelu -> fp32 H ; EPI 1: + bias -> fp32 out
// ---------------------------------------------------------------------------
#define IBM 128
#define IBN 128
#define IBK 64
#define IROW 80
#define ITILE (128 * IROW)                    // 10240 per slice-matrix
#define ISTAGE_B (4 * ITILE)                  // 40960 (A1,A0,B1,B0)
#define IGEMM_SMEM (2 * ISTAGE_B)             // 81920

__device__ __forceinline__ void load_stage_i(uint32_t sb,
                                             const int8_t* __restrict__ A1,
                                             const int8_t* __restrict__ A0,
                                             const int8_t* __restrict__ B1,
                                             const int8_t* __restrict__ B0,
                                             int m0, int n0, int kc, int K, int tid) {
    const int r = tid >> 2, c = tid & 3;       // 512 threads: 128 rows x 4 chunks
    const uint32_t so = (uint32_t)(r * IROW + c * 16);
    const size_t ga = (size_t)(m0 + r) * K + kc + c * 16;
    const size_t gb = (size_t)(n0 + r) * K + kc + c * 16;
    cp16(sb + so,             A1 + ga);
    cp16(sb + ITILE + so,     A0 + ga);
    cp16(sb + 2 * ITILE + so, B1 + gb);
    cp16(sb + 3 * ITILE + so, B0 + gb);
}

template<int EPI, int K, int LDC>
__global__ void __launch_bounds__(512, 1) gemm_imma(
    const int8_t* __restrict__ A1, const int8_t* __restrict__ A0,
    const int8_t* __restrict__ B1, const int8_t* __restrict__ B0,
    const float* __restrict__ SA, const float* __restrict__ SB,
    float* __restrict__ C, const float* __restrict__ bias) {
    extern __shared__ char smem[];
    const uint32_t sb = smem_u32(smem);
    const int tid = threadIdx.x;
    const int lane = tid & 31;
    const int wid = tid >> 5;
    const int wm = wid & 3;            // 4 warps along M (32 rows)
    const int wn = wid >> 2;           // 4 warps along N (32 cols)
    const int m0 = blockIdx.y * IBM;
    const int n0 = blockIdx.x * IBN;

    int acc11[2][4][4], accX[2][4][4];
    #pragma unroll
    for (int i = 0; i < 2; i++)
        #pragma unroll
        for (int j = 0; j < 4; j++)
            #pragma unroll
            for (int q = 0; q < 4; q++) { acc11[i][j][q] = 0; accX[i][j][q] = 0; }

    const int NT = K / IBK;

    load_stage_i(sb, A1, A0, B1, B0, m0, n0, 0, K, tid);
    CP_COMMIT();
    load_stage_i(sb + ISTAGE_B, A1, A0, B1, B0, m0, n0, IBK, K, tid);
    CP_COMMIT();
    CP_WAIT(1);
    __syncthreads();

    const uint32_t a_base = (uint32_t)((wm * 32 + (lane & 15)) * IROW + ((lane >> 4) << 4));
    const uint32_t b_base = (uint32_t)(2 * ITILE +
        (wn * 32 + (lane & 7) + ((lane >> 4) << 3)) * IROW + (((lane >> 3) & 1) << 4));

    for (int t = 0; t < NT; t++) {
        const uint32_t st = sb + (t & 1) * ISTAGE_B;
        #pragma unroll
        for (int kk = 0; kk < 2; kk++) {       // two k32 sections per stage
            uint32_t a1[2][4], a0[2][4], b1[2][4], b0[2][4];
            #pragma unroll
            for (int mt = 0; mt < 2; mt++) {
                const uint32_t aa = st + a_base + mt * 16 * IROW + kk * 32;
                LDSM4(a1[mt][0], a1[mt][1], a1[mt][2], a1[mt][3], aa);
                LDSM4(a0[mt][0], a0[mt][1], a0[mt][2], a0[mt][3], aa + ITILE);
            }
            #pragma unroll
            for (int np = 0; np < 2; np++) {
                const uint32_t ba = st + b_base + np * 16 * IROW + kk * 32;
                LDSM4(b1[np][0], b1[np][1], b1[np][2], b1[np][3], ba);
                LDSM4(b0[np][0], b0[np][1], b0[np][2], b0[np][3], ba + ITILE);
            }
            #pragma unroll
            for (int mt = 0; mt < 2; mt++) {
                #pragma unroll
                for (int np = 0; np < 2; np++) {
                    #pragma unroll
                    for (int h = 0; h < 2; h++) {
                        const int idx = np * 2 + h;
                        MMA_S8(acc11[mt][idx], a1[mt], b1[np][2 * h], b1[np][2 * h + 1]);
                        MMA_S8(accX[mt][idx],  a1[mt], b0[np][2 * h], b0[np][2 * h + 1]);
                        MMA_S8(accX[mt][idx],  a0[mt], b1[np][2 * h], b1[np][2 * h + 1]);
                    }
                }
            }
        }
        if (t + 1 < NT) {
            CP_WAIT(0);                 // stage t+1 resident
            __syncthreads();            // all warps done reading stage t
            if (t + 2 < NT) {
                load_stage_i(sb + (t & 1) * ISTAGE_B, A1, A0, B1, B0,
                             m0, n0, (t + 2) * IBK, K, tid);
                CP_COMMIT();
            }
        }
    }

    // ---- epilogue
    const float inv254 = 1.0f / 254.0f;
    #pragma unroll
    for (int mt = 0; mt < 2; mt++) {
        const int r0 = m0 + wm * 32 + mt * 16 + (lane >> 2);
        const float sa0 = __ldg(SA + r0);
        const float sa1 = __ldg(SA + r0 + 8);
        #pragma unroll
        for (int idx = 0; idx < 4; idx++) {
            const int col = n0 + wn * 32 + idx * 8 + (lane & 3) * 2;
            const float sb0 = __ldg(SB + col);
            const float sb1 = __ldg(SB + col + 1);
            const int* c11 = acc11[mt][idx];
            const int* cx  = accX[mt][idx];
            float v00 = ((float)c11[0] + (float)cx[0] * inv254) * (sa0 * sb0);
            float v01 = ((float)c11[1] + (float)cx[1] * inv254) * (sa0 * sb1);
            float v10 = ((float)c11[2] + (float)cx[2] * inv254) * (sa1 * sb0);
            float v11 = ((float)c11[3] + (float)cx[3] * inv254) * (sa1 * sb1);
            if (EPI == 0) {
                v00 = 0.5f * v00 * (1.0f + erff(v00 * 0.70710678118654752f));
                v01 = 0.5f * v01 * (1.0f + erff(v01 * 0.70710678118654752f));
                v10 = 0.5f * v10 * (1.0f + erff(v10 * 0.70710678118654752f));
                v11 = 0.5f * v11 * (1.0f + erff(v11 * 0.70710678118654752f));
            } else {
                const float b0 = __ldg(bias + col);
                const float b1v = __ldg(bias + col + 1);
                v00 += b0; v01 += b1v; v10 += b0; v11 += b1v;
            }
            *(float2*)(C + (size_t)r0 * LDC + col)       = make_float2(v00, v01);
            *(float2*)(C + (size_t)(r0 + 8) * LDC + col) = make_float2(v10, v11);
        }
    }
}

// ---------------------------------------------------------------------------
// Launcher (graph-capturable)
// ---------------------------------------------------------------------------
extern "C" void kernel_launch(void* const* d_in, const int* in_sizes, int n_in,
                              void* d_out, int out_size) {
    const float* x        = (const float*)d_in[0];
    const float* hra_u    = (const float*)d_in[1];
    const float* W_random = (const float*)d_in[2];
    const float* W_out    = (const float*)d_in[3];
    const float* bias     = (const float*)d_in[4];
    float*       out      = (float*)d_out;

    float *u_p, *sxq, *swt, *swo, *sh, *h_p;
    int8_t *xq1, *xq0, *wt1, *wt0, *wo1, *wo0, *h1, *h0;
    cudaGetSymbolAddress((void**)&u_p, g_u);
    cudaGetSymbolAddress((void**)&xq1, g_xq1);
    cudaGetSymbolAddress((void**)&xq0, g_xq0);
    cudaGetSymbolAddress((void**)&sxq, g_sxq);
    cudaGetSymbolAddress((void**)&wt1, g_wt1);
    cudaGetSymbolAddress((void**)&wt0, g_wt0);
    cudaGetSymbolAddress((void**)&swt, g_swt);
    cudaGetSymbolAddress((void**)&wo1, g_wo1);
    cudaGetSymbolAddress((void**)&wo0, g_wo0);
    cudaGetSymbolAddress((void**)&swo, g_swo);
    cudaGetSymbolAddress((void**)&h_p, g_h);
    cudaGetSymbolAddress((void**)&h1,  g_h1);
    cudaGetSymbolAddress((void**)&h0,  g_h0);
    cudaGetSymbolAddress((void**)&sh,  g_sh);

    cudaFuncSetAttribute((const void*)gemm_imma<0, D_IN, D_HID>,
                         cudaFuncAttributeMaxDynamicSharedMemorySize, IGEMM_SMEM);
    cudaFuncSetAttribute((const void*)gemm_imma<1, D_HID, D_OUT>,
                         cudaFuncAttributeMaxDynamicSharedMemorySize, IGEMM_SMEM);

    // weight prep
    colmax_scale_kernel<<<D_HID / 256, 256>>>(W_random, D_IN, D_HID, swt);
    transpose_quant_kernel<<<dim3(D_HID / 32, D_IN / 32), dim3(32, 8)>>>(
        W_random, swt, wt1, wt0, D_IN, D_HID);
    colmax_scale_kernel<<<D_OUT / 256, 256>>>(W_out, D_HID, D_OUT, swo);
    transpose_quant_kernel<<<dim3(D_OUT / 32, D_HID / 32), dim3(32, 8)>>>(
        W_out, swo, wo1, wo0, D_HID, D_OUT);

    // activations
    gs_kernel<<<1, 256>>>(hra_u, u_p);
    hh_quant_kernel<<<N_ROWS, 256>>>(x, u_p, xq1, xq0, sxq);

    // GEMM1: h = gelu(xq @ Wt^T)   M=4096, N=8192, K=2048
    gemm_imma<0, D_IN, D_HID><<<dim3(D_HID / IBN, N_ROWS / IBM), 512, IGEMM_SMEM>>>(
        xq1, xq0, wt1, wt0, sxq, swt, h_p, nullptr);

    // quantize h rows
    quant_rows_kernel<<<N_ROWS, 256>>>(h_p, h1, h0, sh, D_HID);

    // GEMM2: out = h @ Wo^T + bias   M=4096, N=2048, K=8192
    gemm_imma<1, D_HID, D_OUT><<<dim3(D_OUT / IBN, N_ROWS / IBM), 512, IGEMM_SMEM>>>(
        h1, h0, wo1, wo0, sh, swo, out, bias);
}

// round 8
// speedup vs baseline: 2.5847x; 2.5847x over previous
#include <cuda_runtime.h>
#include <cuda_fp16.h>
#include <math.h>
#include <stdint.h>

#define N_ROWS 4096
#define D_IN   2048
#define D_HID  8192
#define D_OUT  2048
#define RANK   8

// ---------------------------------------------------------------------------
// Static device scratch
// ---------------------------------------------------------------------------
__device__ float g_u[RANK * D_IN];
__device__ __align__(128) __half g_xq_hi[(size_t)N_ROWS * D_IN];
__device__ __align__(128) __half g_xq_lo[(size_t)N_ROWS * D_IN];
__device__ __align__(128) __half g_wt[(size_t)D_HID * D_IN];    // W_random^T fp16
__device__ __align__(128) __half g_wo[(size_t)D_OUT * D_HID];   // W_out^T fp16
__device__ __align__(128) __half g_h_hi[(size_t)N_ROWS * D_HID];
__device__ __align__(128) __half g_h_lo[(size_t)N_ROWS * D_HID];

// ---------------------------------------------------------------------------
// PTX helpers
// ---------------------------------------------------------------------------
__device__ __forceinline__ uint32_t smem_u32(const void* p) {
    uint32_t a;
    asm("{ .reg .u64 t; cvta.to.shared.u64 t, %1; cvt.u32.u64 %0, t; }" : "=r"(a) : "l"(p));
    return a;
}
__device__ __forceinline__ void cp16(uint32_t s, const void* g) {
    asm volatile("cp.async.cg.shared.global [%0], [%1], 16;" :: "r"(s), "l"(g));
}
#define CP_COMMIT() asm volatile("cp.async.commit_group;" ::: "memory")
#define CP_WAIT(n)  asm volatile("cp.async.wait_group %0;" :: "n"(n) : "memory")

#define LDSM4(r0, r1, r2, r3, addr) \
    asm volatile("ldmatrix.sync.aligned.m8n8.x4.shared.b16 {%0,%1,%2,%3}, [%4];" \
                 : "=r"(r0), "=r"(r1), "=r"(r2), "=r"(r3) : "r"(addr))

#define MMA_F16(c, a, b0, b1) \
    asm volatile("mma.sync.aligned.m16n8k16.row.col.f32.f16.f16.f32 " \
                 "{%0,%1,%2,%3},{%4,%5,%6,%7},{%8,%9},{%0,%1,%2,%3};" \
                 : "+f"((c)[0]), "+f"((c)[1]), "+f"((c)[2]), "+f"((c)[3]) \
                 : "r"((a)[0]), "r"((a)[1]), "r"((a)[2]), "r"((a)[3]), "r"(b0), "r"(b1))

// ---------------------------------------------------------------------------
// Block reduction (256 threads)
// ---------------------------------------------------------------------------
__device__ __forceinline__ float blockReduceSum256(float v, float* sred) {
    #pragma unroll
    for (int o = 16; o > 0; o >>= 1) v += __shfl_down_sync(0xffffffffu, v, o);
    const int lane = threadIdx.x & 31;
    const int warp = threadIdx.x >> 5;
    if (lane == 0) sred[warp] = v;
    __syncthreads();
    if (threadIdx.x == 0) {
        float r = sred[0];
        #pragma unroll
        for (int i = 1; i < 8; i++) r += sred[i];
        sred[0] = r;
    }
    __syncthreads();
    float r = sred[0];
    __syncthreads();
    return r;
}

// ---------------------------------------------------------------------------
// 1) Modified Gram-Schmidt (matches reference order and eps)
// ---------------------------------------------------------------------------
__global__ void gs_kernel(const float* __restrict__ hra_u, float* __restrict__ u_out) {
    __shared__ float cur[D_IN];
    __shared__ float sred[8];
    const int tid = threadIdx.x;

    for (int i = 0; i < RANK; i++) {
        for (int d = tid; d < D_IN; d += 256) cur[d] = hra_u[(size_t)d * RANK + i];
        __syncthreads();
        for (int j = 0; j < i; j++) {
            const float* uj = u_out + (size_t)j * D_IN;
            float local = 0.f;
            for (int d = tid; d < D_IN; d += 256) local += uj[d] * cur[d];
            float dot = blockReduceSum256(local, sred);
            for (int d = tid; d < D_IN; d += 256) cur[d] -= dot * uj[d];
            __syncthreads();
        }
        float local = 0.f;
        for (int d = tid; d < D_IN; d += 256) local += cur[d] * cur[d];
        float nrm2 = blockReduceSum256(local, sred);
        float inv = 1.0f / (sqrtf(nrm2) + 1e-6f);
        for (int d = tid; d < D_IN; d += 256) u_out[(size_t)i * D_IN + d] = cur[d] * inv;
        __syncthreads();
    }
}

// ---------------------------------------------------------------------------
// 2) x @ Q via Householder reflections; emit fp16 hi/lo split
// ---------------------------------------------------------------------------
__global__ void __launch_bounds__(256) hh_kernel(const float* __restrict__ x,
                                                 const float* __restrict__ u,
                                                 __half* __restrict__ xq_hi,
                                                 __half* __restrict__ xq_lo) {
    __shared__ float sred[8];
    const int row = blockIdx.x;
    const int tid = threadIdx.x;
    const float* xr = x + (size_t)row * D_IN;

    float v[8];
    #pragma unroll
    for (int j = 0; j < 8; j++) v[j] = xr[tid + j * 256];

    for (int i = 0; i < RANK; i++) {
        const float* ui = u + (size_t)i * D_IN;
        float uu[8];
        #pragma unroll
        for (int j = 0; j < 8; j++) uu[j] = ui[tid + j * 256];
        float local = 0.f;
        #pragma unroll
        for (int j = 0; j < 8; j++) local += v[j] * uu[j];
        float dot = blockReduceSum256(local, sred);
        float s = 2.0f * dot;
        #pragma unroll
        for (int j = 0; j < 8; j++) v[j] -= s * uu[j];
    }

    #pragma unroll
    for (int j = 0; j < 8; j++) {
        size_t o = (size_t)row * D_IN + tid + j * 256;
        __half h = __float2half_rn(v[j]);
        xq_hi[o] = h;
        xq_lo[o] = __float2half_rn(v[j] - __half2float(h));
    }
}

// ---------------------------------------------------------------------------
// 3) Transpose to fp16: in[R,C] fp32 -> out[C,R] fp16
// ---------------------------------------------------------------------------
__global__ void __launch_bounds__(256) transpose_half_kernel(
    const float* __restrict__ in, __half* __restrict__ outp, int R, int C) {
    __shared__ float tile[32][33];
    const int c0 = blockIdx.x * 32, r0 = blockIdx.y * 32;
    const int tx = threadIdx.x, ty = threadIdx.y;
    #pragma unroll
    for (int j = 0; j < 32; j += 8)
        tile[ty + j][tx] = in[(size_t)(r0 + ty + j) * C + c0 + tx];
    __syncthreads();
    #pragma unroll
    for (int j = 0; j < 32; j += 8) {
        float v = tile[tx][ty + j];
        outp[(size_t)(c0 + ty + j) * R + r0 + tx] = __float2half_rn(v);
    }
}

// ---------------------------------------------------------------------------
// 4) HMMA GEMM: C[M,N] = (Ahi + Alo)[M,K] * B[N,K]^T, fp16, fp32 accum.
//    Block 128x128, BK=32, 8 warps (2 M x 4 N), warp tile 64x32,
//    2-stage cp.async, 2 CTAs/SM. 80B-padded rows (conflict-free ldmatrix).
//    EPI 0: gelu -> fp16 hi/lo out (ldc = D_HID)
//    EPI 1: + bias -> fp32 out     (ldc = D_OUT)
// ---------------------------------------------------------------------------
#define BM 128
#define BN 128
#define BK 32
#define LDS_ROW 80
#define TILE_BYTES  (128 * LDS_ROW)             // 10240
#define STAGE_BYTES (3 * TILE_BYTES)            // 30720: Ahi, Alo, B
#define GEMM_SMEM (2 * STAGE_BYTES)             // 61440 -> 2 CTAs/SM

__device__ __forceinline__ void load_stage(uint32_t sb,
                                           const __half* __restrict__ Ahi,
                                           const __half* __restrict__ Alo,
                                           const __half* __restrict__ B,
                                           int m0, int n0, int kc, int K, int tid) {
    #pragma unroll
    for (int i = 0; i < 2; i++) {
        const int id = tid + i * 256;     // 512 16B-chunks per tile
        const int r = id >> 2;
        const int c = id & 3;
        const size_t ga = (size_t)(m0 + r) * K + kc + c * 8;
        const size_t gb = (size_t)(n0 + r) * K + kc + c * 8;
        const uint32_t so = (uint32_t)(r * LDS_ROW + c * 16);
        cp16(sb + so,                  Ahi + ga);
        cp16(sb + TILE_BYTES + so,     Alo + ga);
        cp16(sb + 2 * TILE_BYTES + so, B + gb);
    }
}

template<int EPI>
__global__ void __launch_bounds__(256, 2) gemm_hmma_a2(
    const __half* __restrict__ Ahi, const __half* __restrict__ Alo,
    const __half* __restrict__ B,
    float* __restrict__ Cf, __half* __restrict__ Chi, __half* __restrict__ Clo,
    const float* __restrict__ bias, int K, int ldc) {
    extern __shared__ char smem[];
    const uint32_t sb = smem_u32(smem);
    const int tid = threadIdx.x;
    const int lane = tid & 31;
    const int wid = tid >> 5;
    const int wm = wid & 1;           // 2 warps along M (64 rows each)
    const int wn = wid >> 1;          // 4 warps along N (32 cols each)
    const int m0 = blockIdx.y * BM;
    const int n0 = blockIdx.x * BN;

    float acc[4][4][4];               // [mt][nt][frag]
    #pragma unroll
    for (int i = 0; i < 4; i++)
        #pragma unroll
        for (int j = 0; j < 4; j++)
            #pragma unroll
            for (int q = 0; q < 4; q++) acc[i][j][q] = 0.f;

    const int NT = K / BK;

    load_stage(sb, Ahi, Alo, B, m0, n0, 0, K, tid);
    CP_COMMIT();

    const uint32_t a_base = (uint32_t)((wm * 64 + (lane & 15)) * LDS_ROW + ((lane >> 4) << 4));
    const uint32_t b_base = (uint32_t)(2 * TILE_BYTES +
        (wn * 32 + (lane & 7) + ((lane >> 4) << 3)) * LDS_ROW + (((lane >> 3) & 1) << 4));

    for (int t = 0; t < NT; t++) {
        CP_WAIT(0);                    // stage t resident
        __syncthreads();

        if (t + 1 < NT)
            load_stage(sb + ((t + 1) & 1) * STAGE_BYTES, Ahi, Alo, B,
                       m0, n0, (t + 1) * BK, K, tid);
        CP_COMMIT();

        const uint32_t st = sb + (t & 1) * STAGE_BYTES;
        #pragma unroll
        for (int k16 = 0; k16 < 2; k16++) {
            uint32_t ah[4][4], al[4][4], bh[2][4];
            #pragma unroll
            for (int mt = 0; mt < 4; mt++) {
                const uint32_t aa = st + a_base + mt * 16 * LDS_ROW + k16 * 32;
                LDSM4(ah[mt][0], ah[mt][1], ah[mt][2], ah[mt][3], aa);
                LDSM4(al[mt][0], al[mt][1], al[mt][2], al[mt][3], aa + TILE_BYTES);
            }
            #pragma unroll
            for (int np = 0; np < 2; np++) {
                const uint32_t ba = st + b_base + np * 16 * LDS_ROW + k16 * 32;
                LDSM4(bh[np][0], bh[np][1], bh[np][2], bh[np][3], ba);
            }
            #pragma unroll
            for (int mt = 0; mt < 4; mt++) {
                #pragma unroll
                for (int np = 0; np < 2; np++) {
                    MMA_F16(acc[mt][2 * np],     ah[mt], bh[np][0], bh[np][1]);
                    MMA_F16(acc[mt][2 * np],     al[mt], bh[np][0], bh[np][1]);
                    MMA_F16(acc[mt][2 * np + 1], ah[mt], bh[np][2], bh[np][3]);
                    MMA_F16(acc[mt][2 * np + 1], al[mt], bh[np][2], bh[np][3]);
                }
            }
        }
        __syncthreads();               // all reads of stage t done before overwrite
    }

    // ---- epilogue (register fragments -> global)
    #pragma unroll
    for (int mt = 0; mt < 4; mt++) {
        const int r0 = m0 + wm * 64 + mt * 16 + (lane >> 2);
        #pragma unroll
        for (int nt = 0; nt < 4; nt++) {
            const int col = n0 + wn * 32 + nt * 8 + (lane & 3) * 2;
            const float* a4 = acc[mt][nt];
            if (EPI == 0) {
                #pragma unroll
                for (int h = 0; h < 2; h++) {
                    const int rr = r0 + h * 8;
                    float v0 = a4[2 * h + 0], v1 = a4[2 * h + 1];
                    v0 = 0.5f * v0 * (1.0f + erff(v0 * 0.70710678118654752f));
                    v1 = 0.5f * v1 * (1.0f + erff(v1 * 0.70710678118654752f));
                    __half h0 = __float2half_rn(v0);
                    __half h1 = __float2half_rn(v1);
                    __half l0 = __float2half_rn(v0 - __half2float(h0));
                    __half l1 = __float2half_rn(v1 - __half2float(h1));
                    uint32_t ph = (uint32_t)__half_as_ushort(h0) |
                                  ((uint32_t)__half_as_ushort(h1) << 16);
                    uint32_t pl = (uint32_t)__half_as_ushort(l0) |
                                  ((uint32_t)__half_as_ushort(l1) << 16);
                    *(uint32_t*)(Chi + (size_t)rr * ldc + col) = ph;
                    *(uint32_t*)(Clo + (size_t)rr * ldc + col) = pl;
                }
            } else {
                const float b0 = __ldg(bias + col);
                const float b1 = __ldg(bias + col + 1);
                #pragma unroll
                for (int h = 0; h < 2; h++) {
                    const int rr = r0 + h * 8;
                    float2 v;
                    v.x = a4[2 * h + 0] + b0;
                    v.y = a4[2 * h + 1] + b1;
                    *(float2*)(Cf + (size_t)rr * ldc + col) = v;
                }
            }
        }
    }
}

// ---------------------------------------------------------------------------
// Launcher. Profiled launch (index 3) is GEMM1:
//   0: transpose(W_random)  1: gs  2: hh  3: GEMM1  4: transpose(W_out)  5: GEMM2
// ---------------------------------------------------------------------------
extern "C" void kernel_launch(void* const* d_in, const int* in_sizes, int n_in,
                              void* d_out, int out_size) {
    const float* x        = (const float*)d_in[0];
    const float* hra_u    = (const float*)d_in[1];
    const float* W_random = (const float*)d_in[2];
    const float* W_out    = (const float*)d_in[3];
    const float* bias     = (const float*)d_in[4];
    float*       out      = (float*)d_out;

    float *u_p; __half *xqh, *xql, *wt, *wo, *hh, *hl;
    cudaGetSymbolAddress((void**)&u_p, g_u);
    cudaGetSymbolAddress((void**)&xqh, g_xq_hi);
    cudaGetSymbolAddress((void**)&xql, g_xq_lo);
    cudaGetSymbolAddress((void**)&wt,  g_wt);
    cudaGetSymbolAddress((void**)&wo,  g_wo);
    cudaGetSymbolAddress((void**)&hh,  g_h_hi);
    cudaGetSymbolAddress((void**)&hl,  g_h_lo);

    cudaFuncSetAttribute(gemm_hmma_a2<0>, cudaFuncAttributeMaxDynamicSharedMemorySize, GEMM_SMEM);
    cudaFuncSetAttribute(gemm_hmma_a2<1>, cudaFuncAttributeMaxDynamicSharedMemorySize, GEMM_SMEM);

    transpose_half_kernel<<<dim3(D_HID / 32, D_IN / 32), dim3(32, 8)>>>(W_random, wt, D_IN, D_HID);
    gs_kernel<<<1, 256>>>(hra_u, u_p);
    hh_kernel<<<N_ROWS, 256>>>(x, u_p, xqh, xql);

    // GEMM1: h = gelu(xq @ Wt^T)   M=4096, N=8192, K=2048
    gemm_hmma_a2<0><<<dim3(D_HID / BN, N_ROWS / BM), 256, GEMM_SMEM>>>(
        xqh, xql, wt, nullptr, hh, hl, nullptr, D_IN, D_HID);

    transpose_half_kernel<<<dim3(D_OUT / 32, D_HID / 32), dim3(32, 8)>>>(W_out, wo, D_HID, D_OUT);

    // GEMM2: out = h @ Wo^T + bias   M=4096, N=2048, K=8192
    gemm_hmma_a2<1><<<dim3(D_OUT / BN, N_ROWS / BM), 256, GEMM_SMEM>>>(
        hh, hl, wo, out, nullptr, nullptr, bias, D_HID, D_OUT);
}

// round 9
// speedup vs baseline: 8.4510x; 3.2696x over previous
#include <cuda_runtime.h>
#include <cuda_fp16.h>
#include <math.h>
#include <stdint.h>

#define N_ROWS 4096
#define D_IN   2048
#define D_HID  8192
#define D_OUT  2048
#define RANK   8

// ---------------------------------------------------------------------------
// Static device scratch
// ---------------------------------------------------------------------------
__device__ float g_u[RANK * D_IN];
__device__ __align__(128) __half g_xq[(size_t)N_ROWS * D_IN];
__device__ __align__(128) __half g_wt[(size_t)D_HID * D_IN];    // W_random^T fp16
__device__ __align__(128) __half g_wo[(size_t)D_OUT * D_HID];   // W_out^T fp16
__device__ __align__(128) __half g_h[(size_t)N_ROWS * D_HID];   // gelu(h) fp16

// ---------------------------------------------------------------------------
// PTX helpers
// ---------------------------------------------------------------------------
__device__ __forceinline__ uint32_t smem_u32(const void* p) {
    uint32_t a;
    asm("{ .reg .u64 t; cvta.to.shared.u64 t, %1; cvt.u32.u64 %0, t; }" : "=r"(a) : "l"(p));
    return a;
}
__device__ __forceinline__ void cp16(uint32_t s, const void* g) {
    asm volatile("cp.async.cg.shared.global [%0], [%1], 16;" :: "r"(s), "l"(g));
}
#define CP_COMMIT() asm volatile("cp.async.commit_group;" ::: "memory")
#define CP_WAIT(n)  asm volatile("cp.async.wait_group %0;" :: "n"(n) : "memory")

#define LDSM4(r0, r1, r2, r3, addr) \
    asm volatile("ldmatrix.sync.aligned.m8n8.x4.shared.b16 {%0,%1,%2,%3}, [%4];" \
                 : "=r"(r0), "=r"(r1), "=r"(r2), "=r"(r3) : "r"(addr))

#define MMA_F16(c, a, b0, b1) \
    asm volatile("mma.sync.aligned.m16n8k16.row.col.f32.f16.f16.f32 " \
                 "{%0,%1,%2,%3},{%4,%5,%6,%7},{%8,%9},{%0,%1,%2,%3};" \
                 : "+f"((c)[0]), "+f"((c)[1]), "+f"((c)[2]), "+f"((c)[3]) \
                 : "r"((a)[0]), "r"((a)[1]), "r"((a)[2]), "r"((a)[3]), "r"(b0), "r"(b1))

// ---------------------------------------------------------------------------
// Block reduction (256 threads)
// ---------------------------------------------------------------------------
__device__ __forceinline__ float blockReduceSum256(float v, float* sred) {
    #pragma unroll
    for (int o = 16; o > 0; o >>= 1) v += __shfl_down_sync(0xffffffffu, v, o);
    const int lane = threadIdx.x & 31;
    const int warp = threadIdx.x >> 5;
    if (lane == 0) sred[warp] = v;
    __syncthreads();
    if (threadIdx.x == 0) {
        float r = sred[0];
        #pragma unroll
        for (int i = 1; i < 8; i++) r += sred[i];
        sred[0] = r;
    }
    __syncthreads();
    float r = sred[0];
    __syncthreads();
    return r;
}

// ---------------------------------------------------------------------------
// 1) Modified Gram-Schmidt (matches reference order and eps)
// ---------------------------------------------------------------------------
__global__ void gs_kernel(const float* __restrict__ hra_u, float* __restrict__ u_out) {
    __shared__ float cur[D_IN];
    __shared__ float sred[8];
    const int tid = threadIdx.x;

    for (int i = 0; i < RANK; i++) {
        for (int d = tid; d < D_IN; d += 256) cur[d] = hra_u[(size_t)d * RANK + i];
        __syncthreads();
        for (int j = 0; j < i; j++) {
            const float* uj = u_out + (size_t)j * D_IN;
            float local = 0.f;
            for (int d = tid; d < D_IN; d += 256) local += uj[d] * cur[d];
            float dot = blockReduceSum256(local, sred);
            for (int d = tid; d < D_IN; d += 256) cur[d] -= dot * uj[d];
            __syncthreads();
        }
        float local = 0.f;
        for (int d = tid; d < D_IN; d += 256) local += cur[d] * cur[d];
        float nrm2 = blockReduceSum256(local, sred);
        float inv = 1.0f / (sqrtf(nrm2) + 1e-6f);
        for (int d = tid; d < D_IN; d += 256) u_out[(size_t)i * D_IN + d] = cur[d] * inv;
        __syncthreads();
    }
}

// ---------------------------------------------------------------------------
// 2) x @ Q via Householder reflections; emit fp16
// ---------------------------------------------------------------------------
__global__ void __launch_bounds__(256) hh_kernel(const float* __restrict__ x,
                                                 const float* __restrict__ u,
                                                 __half* __restrict__ xq) {
    __shared__ float sred[8];
    const int row = blockIdx.x;
    const int tid = threadIdx.x;
    const float* xr = x + (size_t)row * D_IN;

    float v[8];
    #pragma unroll
    for (int j = 0; j < 8; j++) v[j] = xr[tid + j * 256];

    for (int i = 0; i < RANK; i++) {
        const float* ui = u + (size_t)i * D_IN;
        float uu[8];
        #pragma unroll
        for (int j = 0; j < 8; j++) uu[j] = ui[tid + j * 256];
        float local = 0.f;
        #pragma unroll
        for (int j = 0; j < 8; j++) local += v[j] * uu[j];
        float dot = blockReduceSum256(local, sred);
        float s = 2.0f * dot;
        #pragma unroll
        for (int j = 0; j < 8; j++) v[j] -= s * uu[j];
    }

    #pragma unroll
    for (int j = 0; j < 8; j++)
        xq[(size_t)row * D_IN + tid + j * 256] = __float2half_rn(v[j]);
}

// ---------------------------------------------------------------------------
// 3) Transpose to fp16: in[R,C] fp32 -> out[C,R] fp16
// ---------------------------------------------------------------------------
__global__ void __launch_bounds__(256) transpose_half_kernel(
    const float* __restrict__ in, __half* __restrict__ outp, int R, int C) {
    __shared__ float tile[32][33];
    const int c0 = blockIdx.x * 32, r0 = blockIdx.y * 32;
    const int tx = threadIdx.x, ty = threadIdx.y;
    #pragma unroll
    for (int j = 0; j < 32; j += 8)
        tile[ty + j][tx] = in[(size_t)(r0 + ty + j) * C + c0 + tx];
    __syncthreads();
    #pragma unroll
    for (int j = 0; j < 32; j += 8) {
        float v = tile[tx][ty + j];
        outp[(size_t)(c0 + ty + j) * R + r0 + tx] = __float2half_rn(v);
    }
}

// ---------------------------------------------------------------------------
// 4) HMMA GEMM: C[M,N] = A[M,K] * B[N,K]^T, fp16 single-term, fp32 accum.
//    Block 128x128, BK=64, 8 warps (2 M x 4 N), warp tile 64x32.
//    3-stage cp.async (CP_WAIT(1)), 2 CTAs/SM, SW128 XOR swizzle, 128B rows.
//    EPI 0: gelu -> fp16 out (ldc = D_HID) ; EPI 1: + bias -> fp32 (ldc = D_OUT)
// ---------------------------------------------------------------------------
#define BM 128
#define BN 128
#define BK 64
#define STAGES 3
#define ROW_B 128                               // 64 fp16 = 128 B exactly
#define TILE_BYTES  (128 * ROW_B)               // 16384
#define STAGE_BYTES (2 * TILE_BYTES)            // 32768: A, B
#define GEMM_SMEM (STAGES * STAGE_BYTES)        // 98304 -> 2 CTAs/SM

__device__ __forceinline__ uint32_t swz(uint32_t off) { return off ^ ((off >> 3) & 0x70); }

__device__ __forceinline__ void load_stage(uint32_t sb,
                                           const __half* __restrict__ A,
                                           const __half* __restrict__ B,
                                           int m0, int n0, int kc, int K, int tid) {
    #pragma unroll
    for (int i = 0; i < 4; i++) {
        const int id = tid + i * 256;           // 1024 16B-chunks per tile
        const int r = id >> 3;                  // row 0..127
        const int c = id & 7;                   // 16B chunk 0..7
        const uint32_t so = (uint32_t)(r * ROW_B + (((uint32_t)(c ^ (r & 7))) << 4));
        const size_t ga = (size_t)(m0 + r) * K + kc + c * 8;
        const size_t gb = (size_t)(n0 + r) * K + kc + c * 8;
        cp16(sb + so,              A + ga);
        cp16(sb + TILE_BYTES + so, B + gb);
    }
}

template<int EPI>
__global__ void __launch_bounds__(256, 2) gemm_hmma_f16(
    const __half* __restrict__ A, const __half* __restrict__ B,
    float* __restrict__ Cf, __half* __restrict__ Ch,
    const float* __restrict__ bias, int K, int ldc) {
    extern __shared__ char smem[];
    const uint32_t sb = smem_u32(smem);
    const int tid = threadIdx.x;
    const int lane = tid & 31;
    const int wid = tid >> 5;
    const int wm = wid & 1;           // 2 warps along M (64 rows each)
    const int wn = wid >> 1;          // 4 warps along N (32 cols each)
    const int m0 = blockIdx.y * BM;
    const int n0 = blockIdx.x * BN;

    float acc[4][4][4];               // [mt][nt][frag]
    #pragma unroll
    for (int i = 0; i < 4; i++)
        #pragma unroll
        for (int j = 0; j < 4; j++)
            #pragma unroll
            for (int q = 0; q < 4; q++) acc[i][j][q] = 0.f;

    const int NT = K / BK;

    // prologue: stages 0, 1
    load_stage(sb,               A, B, m0, n0, 0,  K, tid);
    CP_COMMIT();
    load_stage(sb + STAGE_BYTES, A, B, m0, n0, BK, K, tid);
    CP_COMMIT();

    // per-lane ldmatrix bases (tile-relative, swizzled at use)
    const int rowA  = wm * 64 + (lane & 15);
    const uint32_t partA = ((uint32_t)(lane >> 4)) << 4;
    const uint32_t xorA  = ((uint32_t)(rowA & 7)) << 4;
    const int rowB  = wn * 32 + (lane & 7) + ((lane >> 4) << 3);
    const uint32_t partB = ((uint32_t)((lane >> 3) & 1)) << 4;
    const uint32_t xorB  = ((uint32_t)(rowB & 7)) << 4;

    for (int t = 0; t < NT; t++) {
        CP_WAIT(1);                    // stage t resident (t+1 may be in flight)
        __syncthreads();               // also: all warps done reading slot (t-1)%3

        if (t + 2 < NT)
            load_stage(sb + ((t + 2) % STAGES) * STAGE_BYTES,
                       A, B, m0, n0, (t + 2) * BK, K, tid);
        CP_COMMIT();                   // unconditional: keeps group count = 1/iter

        const uint32_t st = sb + (t % STAGES) * STAGE_BYTES;
        #pragma unroll
        for (int kk = 0; kk < 4; kk++) {
            const uint32_t cbA = ((uint32_t)(kk * 32) + partA) ^ xorA;
            const uint32_t cbB = ((uint32_t)(kk * 32) + partB) ^ xorB;
            uint32_t af[4][4], bf[2][4];
            #pragma unroll
            for (int mt = 0; mt < 4; mt++) {
                const uint32_t aa = st + (uint32_t)((rowA + mt * 16) * ROW_B) + cbA;
                LDSM4(af[mt][0], af[mt][1], af[mt][2], af[mt][3], aa);
            }
            #pragma unroll
            for (int np = 0; np < 2; np++) {
                const uint32_t ba = st + TILE_BYTES +
                                    (uint32_t)((rowB + np * 16) * ROW_B) + cbB;
                LDSM4(bf[np][0], bf[np][1], bf[np][2], bf[np][3], ba);
            }
            #pragma unroll
            for (int mt = 0; mt < 4; mt++) {
                #pragma unroll
                for (int np = 0; np < 2; np++) {
                    MMA_F16(acc[mt][2 * np],     af[mt], bf[np][0], bf[np][1]);
                    MMA_F16(acc[mt][2 * np + 1], af[mt], bf[np][2], bf[np][3]);
                }
            }
        }
    }

    // ---- epilogue (register fragments -> global)
    #pragma unroll
    for (int mt = 0; mt < 4; mt++) {
        const int r0 = m0 + wm * 64 + mt * 16 + (lane >> 2);
        #pragma unroll
        for (int nt = 0; nt < 4; nt++) {
            const int col = n0 + wn * 32 + nt * 8 + (lane & 3) * 2;
            const float* a4 = acc[mt][nt];
            if (EPI == 0) {
                #pragma unroll
                for (int h = 0; h < 2; h++) {
                    const int rr = r0 + h * 8;
                    float v0 = a4[2 * h + 0], v1 = a4[2 * h + 1];
                    v0 = 0.5f * v0 * (1.0f + erff(v0 * 0.70710678118654752f));
                    v1 = 0.5f * v1 * (1.0f + erff(v1 * 0.70710678118654752f));
                    uint32_t ph = (uint32_t)__half_as_ushort(__float2half_rn(v0)) |
                                  ((uint32_t)__half_as_ushort(__float2half_rn(v1)) << 16);
                    *(uint32_t*)(Ch + (size_t)rr * ldc + col) = ph;
                }
            } else {
                const float b0 = __ldg(bias + col);
                const float b1 = __ldg(bias + col + 1);
                #pragma unroll
                for (int h = 0; h < 2; h++) {
                    const int rr = r0 + h * 8;
                    float2 v;
                    v.x = a4[2 * h + 0] + b0;
                    v.y = a4[2 * h + 1] + b1;
                    *(float2*)(Cf + (size_t)rr * ldc + col) = v;
                }
            }
        }
    }
}

// ---------------------------------------------------------------------------
// Launcher. Order: transpose(Wr), gs, hh, GEMM1, transpose(Wo), GEMM2
// (profiled launch index lands on GEMM1 as in rounds 6/8)
// ---------------------------------------------------------------------------
extern "C" void kernel_launch(void* const* d_in, const int* in_sizes, int n_in,
                              void* d_out, int out_size) {
    const float* x        = (const float*)d_in[0];
    const float* hra_u    = (const float*)d_in[1];
    const float* W_random = (const float*)d_in[2];
    const float* W_out    = (const float*)d_in[3];
    const float* bias     = (const float*)d_in[4];
    float*       out      = (float*)d_out;

    float* u_p; __half *xq, *wt, *wo, *hp;
    cudaGetSymbolAddress((void**)&u_p, g_u);
    cudaGetSymbolAddress((void**)&xq,  g_xq);
    cudaGetSymbolAddress((void**)&wt,  g_wt);
    cudaGetSymbolAddress((void**)&wo,  g_wo);
    cudaGetSymbolAddress((void**)&hp,  g_h);

    cudaFuncSetAttribute(gemm_hmma_f16<0>, cudaFuncAttributeMaxDynamicSharedMemorySize, GEMM_SMEM);
    cudaFuncSetAttribute(gemm_hmma_f16<1>, cudaFuncAttributeMaxDynamicSharedMemorySize, GEMM_SMEM);

    transpose_half_kernel<<<dim3(D_HID / 32, D_IN / 32), dim3(32, 8)>>>(W_random, wt, D_IN, D_HID);
    gs_kernel<<<1, 256>>>(hra_u, u_p);
    hh_kernel<<<N_ROWS, 256>>>(x, u_p, xq);

    // GEMM1: h = gelu(xq @ Wt^T)   M=4096, N=8192, K=2048
    gemm_hmma_f16<0><<<dim3(D_HID / BN, N_ROWS / BM), 256, GEMM_SMEM>>>(
        xq, wt, nullptr, hp, nullptr, D_IN, D_HID);

    transpose_half_kernel<<<dim3(D_OUT / 32, D_HID / 32), dim3(32, 8)>>>(W_out, wo, D_HID, D_OUT);

    // GEMM2: out = h @ Wo^T + bias   M=4096, N=2048, K=8192
    gemm_hmma_f16<1><<<dim3(D_OUT / BN, N_ROWS / BM), 256, GEMM_SMEM>>>(
        hp, wo, out, nullptr, bias, D_HID, D_OUT);
}

// round 10
// speedup vs baseline: 8.7111x; 1.0308x over previous
#include <cuda_runtime.h>
#include <cuda_fp16.h>
#include <math.h>
#include <stdint.h>

#define N_ROWS 4096
#define D_IN   2048
#define D_HID  8192
#define D_OUT  2048
#define RANK   8

// ---------------------------------------------------------------------------
// Static device scratch
// ---------------------------------------------------------------------------
__device__ float g_u[RANK * D_IN];
__device__ float g_T[64];                                       // WY T (8x8, upper)
__device__ __align__(128) __half g_xq[(size_t)N_ROWS * D_IN];
__device__ __align__(128) __half g_wt[(size_t)D_HID * D_IN];    // W_random^T fp16
__device__ __align__(128) __half g_wo[(size_t)D_OUT * D_HID];   // W_out^T fp16
__device__ __align__(128) __half g_h[(size_t)N_ROWS * D_HID];   // gelu(h) fp16

// ---------------------------------------------------------------------------
// PTX helpers
// ---------------------------------------------------------------------------
__device__ __forceinline__ uint32_t smem_u32(const void* p) {
    uint32_t a;
    asm("{ .reg .u64 t; cvta.to.shared.u64 t, %1; cvt.u32.u64 %0, t; }" : "=r"(a) : "l"(p));
    return a;
}
__device__ __forceinline__ void cp16(uint32_t s, const void* g) {
    asm volatile("cp.async.cg.shared.global [%0], [%1], 16;" :: "r"(s), "l"(g));
}
#define CP_COMMIT() asm volatile("cp.async.commit_group;" ::: "memory")
#define CP_WAIT(n)  asm volatile("cp.async.wait_group %0;" :: "n"(n) : "memory")

#define LDSM4(r0, r1, r2, r3, addr) \
    asm volatile("ldmatrix.sync.aligned.m8n8.x4.shared.b16 {%0,%1,%2,%3}, [%4];" \
                 : "=r"(r0), "=r"(r1), "=r"(r2), "=r"(r3) : "r"(addr))

#define MMA_F16(c, a, b0, b1) \
    asm volatile("mma.sync.aligned.m16n8k16.row.col.f32.f16.f16.f32 " \
                 "{%0,%1,%2,%3},{%4,%5,%6,%7},{%8,%9},{%0,%1,%2,%3};" \
                 : "+f"((c)[0]), "+f"((c)[1]), "+f"((c)[2]), "+f"((c)[3]) \
                 : "r"((a)[0]), "r"((a)[1]), "r"((a)[2]), "r"((a)[3]), "r"(b0), "r"(b1))

// ---------------------------------------------------------------------------
// 1) Gram-Schmidt (batched-CGS; matches reference to ~1e-7) + WY T matrix.
//    Single block, 256 threads, U cached in dynamic smem (8x2048 fp32).
// ---------------------------------------------------------------------------
#define GS_SMEM ((RANK + 1) * D_IN * 4)     // su[8][2048] + cur[2048] = 73728 B

__global__ void gs_kernel(const float* __restrict__ hra_u,
                          float* __restrict__ u_out, float* __restrict__ Tmat) {
    extern __shared__ float sdyn[];
    float* su  = sdyn;                 // [8][D_IN]
    float* cur = sdyn + RANK * D_IN;   // [D_IN]
    __shared__ float swarp[8][8];      // [warp][val]
    __shared__ float sdots[8];
    __shared__ float sredv[8];
    __shared__ float sG[28];

    const int tid  = threadIdx.x;
    const int lane = tid & 31;
    const int warp = tid >> 5;

    for (int i = 0; i < RANK; i++) {
        // load raw column i (each thread owns d = tid + e*256)
        #pragma unroll
        for (int e = 0; e < 8; e++) {
            const int d = tid + e * 256;
            cur[d] = hra_u[(size_t)d * RANK + i];
        }
        __syncthreads();

        if (i > 0) {
            // batched dots: pd[j] = <su[j], cur> for all j < i, one pass
            float pd[7];
            #pragma unroll
            for (int j = 0; j < 7; j++) pd[j] = 0.f;
            #pragma unroll
            for (int e = 0; e < 8; e++) {
                const int d = tid + e * 256;
                const float c = cur[d];
                #pragma unroll
                for (int j = 0; j < 7; j++)
                    if (j < i) pd[j] += su[j * D_IN + d] * c;
            }
            #pragma unroll
            for (int j = 0; j < 7; j++) {
                #pragma unroll
                for (int o = 16; o > 0; o >>= 1)
                    pd[j] += __shfl_down_sync(0xffffffffu, pd[j], o);
            }
            if (lane == 0) {
                #pragma unroll
                for (int j = 0; j < 7; j++) swarp[warp][j] = pd[j];
            }
            __syncthreads();
            if (tid < 7 && tid < i) {
                float s = 0.f;
                #pragma unroll
                for (int w = 0; w < 8; w++) s += swarp[w][tid];
                sdots[tid] = s;
            }
            __syncthreads();
            // subtract projections (threads own their elements)
            #pragma unroll
            for (int e = 0; e < 8; e++) {
                const int d = tid + e * 256;
                float s = 0.f;
                #pragma unroll
                for (int j = 0; j < 7; j++)
                    if (j < i) s += sdots[j] * su[j * D_IN + d];
                cur[d] -= s;
            }
        }

        // norm of own elements -> block reduce
        float nq = 0.f;
        #pragma unroll
        for (int e = 0; e < 8; e++) {
            const int d = tid + e * 256;
            nq += cur[d] * cur[d];
        }
        #pragma unroll
        for (int o = 16; o > 0; o >>= 1) nq += __shfl_down_sync(0xffffffffu, nq, o);
        if (lane == 0) sredv[warp] = nq;
        __syncthreads();
        if (tid == 0) {
            float r = sredv[0];
            #pragma unroll
            for (int w = 1; w < 8; w++) r += sredv[w];
            sredv[0] = 1.0f / (sqrtf(r) + 1e-6f);
        }
        __syncthreads();
        const float inv = sredv[0];
        #pragma unroll
        for (int e = 0; e < 8; e++) {
            const int d = tid + e * 256;
            const float v = cur[d] * inv;
            su[i * D_IN + d] = v;
            u_out[(size_t)i * D_IN + d] = v;
        }
        __syncthreads();
    }

    // ---- Gram matrix upper pairs G[j][k] (j<k), 28 dots in one pass
    {
        float pg[28];
        #pragma unroll
        for (int p = 0; p < 28; p++) pg[p] = 0.f;
        #pragma unroll
        for (int e = 0; e < 8; e++) {
            const int d = tid + e * 256;
            float uj[8];
            #pragma unroll
            for (int j = 0; j < 8; j++) uj[j] = su[j * D_IN + d];
            int p = 0;
            #pragma unroll
            for (int k = 1; k < 8; k++)
                #pragma unroll
                for (int j = 0; j < 8; j++)
                    if (j < k) { pg[p] += uj[j] * uj[k]; p++; }
        }
        __shared__ float swg[8][28];
        #pragma unroll
        for (int p = 0; p < 28; p++) {
            #pragma unroll
            for (int o = 16; o > 0; o >>= 1)
                pg[p] += __shfl_down_sync(0xffffffffu, pg[p], o);
        }
        if (lane == 0) {
            #pragma unroll
            for (int p = 0; p < 28; p++) swg[warp][p] = pg[p];
        }
        __syncthreads();
        if (tid < 28) {
            float s = 0.f;
            #pragma unroll
            for (int w = 0; w < 8; w++) s += swg[w][tid];
            sG[tid] = s;
        }
        __syncthreads();
        if (tid == 0) {
            // T recurrence: Q = I - U T U^T ; T upper-tri
            float T[8][8];
            float G[8][8];
            #pragma unroll
            for (int a = 0; a < 8; a++)
                #pragma unroll
                for (int b = 0; b < 8; b++) { T[a][b] = 0.f; G[a][b] = 0.f; }
            int p = 0;
            for (int k = 1; k < 8; k++)
                for (int j = 0; j < k; j++) { G[j][k] = sG[p]; p++; }
            T[0][0] = 2.0f;
            for (int k = 1; k < 8; k++) {
                for (int j = 0; j < k; j++) {
                    float s = 0.f;
                    for (int l = j; l < k; l++) s += T[j][l] * G[l][k];
                    T[j][k] = -2.0f * s;
                }
                T[k][k] = 2.0f;
            }
            for (int a = 0; a < 8; a++)
                for (int b = 0; b < 8; b++) Tmat[a * 8 + b] = T[a][b];
        }
    }
}

// ---------------------------------------------------------------------------
// 2) x @ Q via WY form: v = x - ((xU) T) U^T. ONE reduction round per row.
// ---------------------------------------------------------------------------
__global__ void __launch_bounds__(256) hh_kernel(const float* __restrict__ x,
                                                 const float* __restrict__ u,
                                                 const float* __restrict__ Tmat,
                                                 __half* __restrict__ xq) {
    __shared__ float swarp[8][8];
    __shared__ float sdots[8];
    __shared__ float sT[64];
    __shared__ float sq[8];
    const int row  = blockIdx.x;
    const int tid  = threadIdx.x;
    const int lane = tid & 31;
    const int warp = tid >> 5;
    const float* xr = x + (size_t)row * D_IN;

    if (tid < 64) sT[tid] = Tmat[tid];

    float v[8];
    #pragma unroll
    for (int e = 0; e < 8; e++) v[e] = xr[tid + e * 256];

    // p[j] = <x, u_j> for all 8 j in one pass
    float pd[8];
    #pragma unroll
    for (int j = 0; j < 8; j++) pd[j] = 0.f;
    #pragma unroll
    for (int e = 0; e < 8; e++) {
        const int d = tid + e * 256;
        const float c = v[e];
        #pragma unroll
        for (int j = 0; j < 8; j++) pd[j] += u[(size_t)j * D_IN + d] * c;
    }
    #pragma unroll
    for (int j = 0; j < 8; j++) {
        #pragma unroll
        for (int o = 16; o > 0; o >>= 1)
            pd[j] += __shfl_down_sync(0xffffffffu, pd[j], o);
    }
    if (lane == 0) {
        #pragma unroll
        for (int j = 0; j < 8; j++) swarp[warp][j] = pd[j];
    }
    __syncthreads();
    if (tid < 8) {
        float s = 0.f;
        #pragma unroll
        for (int w = 0; w < 8; w++) s += swarp[w][tid];
        sdots[tid] = s;
    }
    __syncthreads();
    if (tid < 8) {
        // q[j] = sum_i p[i] * T[i][j]
        float s = 0.f;
        #pragma unroll
        for (int i = 0; i < 8; i++) s += sdots[i] * sT[i * 8 + tid];
        sq[tid] = s;
    }
    __syncthreads();

    float q[8];
    #pragma unroll
    for (int j = 0; j < 8; j++) q[j] = sq[j];

    #pragma unroll
    for (int e = 0; e < 8; e++) {
        const int d = tid + e * 256;
        float s = 0.f;
        #pragma unroll
        for (int j = 0; j < 8; j++) s += q[j] * u[(size_t)j * D_IN + d];
        xq[(size_t)row * D_IN + d] = __float2half_rn(v[e] - s);
    }
}

// ---------------------------------------------------------------------------
// 3) Transpose to fp16: in[R,C] fp32 -> out[C,R] fp16
// ---------------------------------------------------------------------------
__global__ void __launch_bounds__(256) transpose_half_kernel(
    const float* __restrict__ in, __half* __restrict__ outp, int R, int C) {
    __shared__ float tile[32][33];
    const int c0 = blockIdx.x * 32, r0 = blockIdx.y * 32;
    const int tx = threadIdx.x, ty = threadIdx.y;
    #pragma unroll
    for (int j = 0; j < 32; j += 8)
        tile[ty + j][tx] = in[(size_t)(r0 + ty + j) * C + c0 + tx];
    __syncthreads();
    #pragma unroll
    for (int j = 0; j < 32; j += 8) {
        float v = tile[tx][ty + j];
        outp[(size_t)(c0 + ty + j) * R + r0 + tx] = __float2half_rn(v);
    }
}

// ---------------------------------------------------------------------------
// 4) HMMA GEMM: C[M,N] = A[M,K] * B[N,K]^T, fp16, fp32 accum.
//    Block 128x128, BK=64, 8 warps (2 M x 4 N), warp tile 64x32.
//    3-stage cp.async (CP_WAIT(1)), 2 CTAs/SM, SW128 swizzle,
//    register double-buffered ldmatrix fragments.
// ---------------------------------------------------------------------------
#define BM 128
#define BN 128
#define BK 64
#define STAGES 3
#define ROW_B 128
#define TILE_BYTES  (128 * ROW_B)               // 16384
#define STAGE_BYTES (2 * TILE_BYTES)            // 32768
#define GEMM_SMEM (STAGES * STAGE_BYTES)        // 98304 -> 2 CTAs/SM

__device__ __forceinline__ void load_stage(uint32_t sb,
                                           const __half* __restrict__ A,
                                           const __half* __restrict__ B,
                                           int m0, int n0, int kc, int K, int tid) {
    #pragma unroll
    for (int i = 0; i < 4; i++) {
        const int id = tid + i * 256;
        const int r = id >> 3;
        const int c = id & 7;
        const uint32_t so = (uint32_t)(r * ROW_B + (((uint32_t)(c ^ (r & 7))) << 4));
        const size_t ga = (size_t)(m0 + r) * K + kc + c * 8;
        const size_t gb = (size_t)(n0 + r) * K + kc + c * 8;
        cp16(sb + so,              A + ga);
        cp16(sb + TILE_BYTES + so, B + gb);
    }
}

template<int EPI>
__global__ void __launch_bounds__(256, 2) gemm_hmma_f16(
    const __half* __restrict__ A, const __half* __restrict__ B,
    float* __restrict__ Cf, __half* __restrict__ Ch,
    const float* __restrict__ bias, int K, int ldc) {
    extern __shared__ char smem[];
    const uint32_t sb = smem_u32(smem);
    const int tid = threadIdx.x;
    const int lane = tid & 31;
    const int wid = tid >> 5;
    const int wm = wid & 1;
    const int wn = wid >> 1;
    const int m0 = blockIdx.y * BM;
    const int n0 = blockIdx.x * BN;

    float acc[4][4][4];
    #pragma unroll
    for (int i = 0; i < 4; i++)
        #pragma unroll
        for (int j = 0; j < 4; j++)
            #pragma unroll
            for (int q = 0; q < 4; q++) acc[i][j][q] = 0.f;

    const int NT = K / BK;

    load_stage(sb,               A, B, m0, n0, 0,  K, tid);
    CP_COMMIT();
    load_stage(sb + STAGE_BYTES, A, B, m0, n0, BK, K, tid);
    CP_COMMIT();

    const int rowA  = wm * 64 + (lane & 15);
    const uint32_t partA = ((uint32_t)(lane >> 4)) << 4;
    const uint32_t xorA  = ((uint32_t)(rowA & 7)) << 4;
    const int rowB  = wn * 32 + (lane & 7) + ((lane >> 4) << 3);
    const uint32_t partB = ((uint32_t)((lane >> 3) & 1)) << 4;
    const uint32_t xorB  = ((uint32_t)(rowB & 7)) << 4;

    uint32_t af[2][4][4], bf[2][2][4];

#define LOAD_FRAGS(buf, kk, st_) do { \
    const uint32_t cbA = (((uint32_t)(kk) * 32) + partA) ^ xorA; \
    const uint32_t cbB = (((uint32_t)(kk) * 32) + partB) ^ xorB; \
    _Pragma("unroll") \
    for (int mt = 0; mt < 4; mt++) { \
        const uint32_t aa = (st_) + (uint32_t)((rowA + mt * 16) * ROW_B) + cbA; \
        LDSM4(af[buf][mt][0], af[buf][mt][1], af[buf][mt][2], af[buf][mt][3], aa); \
    } \
    _Pragma("unroll") \
    for (int np = 0; np < 2; np++) { \
        const uint32_t ba = (st_) + TILE_BYTES + (uint32_t)((rowB + np * 16) * ROW_B) + cbB; \
        LDSM4(bf[buf][np][0], bf[buf][np][1], bf[buf][np][2], bf[buf][np][3], ba); \
    } \
} while (0)

    for (int t = 0; t < NT; t++) {
        CP_WAIT(1);
        __syncthreads();

        if (t + 2 < NT)
            load_stage(sb + ((t + 2) % STAGES) * STAGE_BYTES,
                       A, B, m0, n0, (t + 2) * BK, K, tid);
        CP_COMMIT();

        const uint32_t st = sb + (t % STAGES) * STAGE_BYTES;
        LOAD_FRAGS(0, 0, st);
        #pragma unroll
        for (int kk = 0; kk < 4; kk++) {
            const int cb = kk & 1;
            if (kk < 3) {
                const int nb = cb ^ 1;
                LOAD_FRAGS(nb, kk + 1, st);
            }
            #pragma unroll
            for (int mt = 0; mt < 4; mt++) {
                #pragma unroll
                for (int np = 0; np < 2; np++) {
                    MMA_F16(acc[mt][2 * np],     af[cb][mt], bf[cb][np][0], bf[cb][np][1]);
                    MMA_F16(acc[mt][2 * np + 1], af[cb][mt], bf[cb][np][2], bf[cb][np][3]);
                }
            }
        }
    }
#undef LOAD_FRAGS

    // ---- epilogue
    #pragma unroll
    for (int mt = 0; mt < 4; mt++) {
        const int r0 = m0 + wm * 64 + mt * 16 + (lane >> 2);
        #pragma unroll
        for (int nt = 0; nt < 4; nt++) {
            const int col = n0 + wn * 32 + nt * 8 + (lane & 3) * 2;
            const float* a4 = acc[mt][nt];
            if (EPI == 0) {
                #pragma unroll
                for (int h = 0; h < 2; h++) {
                    const int rr = r0 + h * 8;
                    float v0 = a4[2 * h + 0], v1 = a4[2 * h + 1];
                    v0 = 0.5f * v0 * (1.0f + erff(v0 * 0.70710678118654752f));
                    v1 = 0.5f * v1 * (1.0f + erff(v1 * 0.70710678118654752f));
                    uint32_t ph = (uint32_t)__half_as_ushort(__float2half_rn(v0)) |
                                  ((uint32_t)__half_as_ushort(__float2half_rn(v1)) << 16);
                    *(uint32_t*)(Ch + (size_t)rr * ldc + col) = ph;
                }
            } else {
                const float b0 = __ldg(bias + col);
                const float b1 = __ldg(bias + col + 1);
                #pragma unroll
                for (int h = 0; h < 2; h++) {
                    const int rr = r0 + h * 8;
                    float2 v;
                    v.x = a4[2 * h + 0] + b0;
                    v.y = a4[2 * h + 1] + b1;
                    *(float2*)(Cf + (size_t)rr * ldc + col) = v;
                }
            }
        }
    }
}

// ---------------------------------------------------------------------------
// Launcher. Order: transpose(Wr), gs, hh, GEMM1, transpose(Wo), GEMM2
// ---------------------------------------------------------------------------
extern "C" void kernel_launch(void* const* d_in, const int* in_sizes, int n_in,
                              void* d_out, int out_size) {
    const float* x        = (const float*)d_in[0];
    const float* hra_u    = (const float*)d_in[1];
    const float* W_random = (const float*)d_in[2];
    const float* W_out    = (const float*)d_in[3];
    const float* bias     = (const float*)d_in[4];
    float*       out      = (float*)d_out;

    float *u_p, *T_p; __half *xq, *wt, *wo, *hp;
    cudaGetSymbolAddress((void**)&u_p, g_u);
    cudaGetSymbolAddress((void**)&T_p, g_T);
    cudaGetSymbolAddress((void**)&xq,  g_xq);
    cudaGetSymbolAddress((void**)&wt,  g_wt);
    cudaGetSymbolAddress((void**)&wo,  g_wo);
    cudaGetSymbolAddress((void**)&hp,  g_h);

    cudaFuncSetAttribute(gs_kernel, cudaFuncAttributeMaxDynamicSharedMemorySize, GS_SMEM);
    cudaFuncSetAttribute(gemm_hmma_f16<0>, cudaFuncAttributeMaxDynamicSharedMemorySize, GEMM_SMEM);
    cudaFuncSetAttribute(gemm_hmma_f16<1>, cudaFuncAttributeMaxDynamicSharedMemorySize, GEMM_SMEM);

    transpose_half_kernel<<<dim3(D_HID / 32, D_IN / 32), dim3(32, 8)>>>(W_random, wt, D_IN, D_HID);
    gs_kernel<<<1, 256, GS_SMEM>>>(hra_u, u_p, T_p);
    hh_kernel<<<N_ROWS, 256>>>(x, u_p, T_p, xq);

    // GEMM1: h = gelu(xq @ Wt^T)   M=4096, N=8192, K=2048
    gemm_hmma_f16<0><<<dim3(D_HID / BN, N_ROWS / BM), 256, GEMM_SMEM>>>(
        xq, wt, nullptr, hp, nullptr, D_IN, D_HID);

    transpose_half_kernel<<<dim3(D_OUT / 32, D_HID / 32), dim3(32, 8)>>>(W_out, wo, D_HID, D_OUT);

    // GEMM2: out = h @ Wo^T + bias   M=4096, N=2048, K=8192
    gemm_hmma_f16<1><<<dim3(D_OUT / BN, N_ROWS / BM), 256, GEMM_SMEM>>>(
        hp, wo, out, nullptr, bias, D_HID, D_OUT);
}

// round 11
// speedup vs baseline: 8.8262x; 1.0132x over previous
#include <cuda_runtime.h>
#include <cuda_fp16.h>
#include <math.h>
#include <stdint.h>

#define N_ROWS 4096
#define D_IN   2048
#define D_HID  8192
#define D_OUT  2048
#define RANK   8

// ---------------------------------------------------------------------------
// Static device scratch
// ---------------------------------------------------------------------------
__device__ float g_u[RANK * D_IN];
__device__ float g_T[64];                                       // WY T (8x8, upper)
__device__ __align__(128) __half g_xq[(size_t)N_ROWS * D_IN];
__device__ __align__(128) __half g_wt[(size_t)D_HID * D_IN];    // W_random^T fp16
__device__ __align__(128) __half g_wo[(size_t)D_OUT * D_HID];   // W_out^T fp16
__device__ __align__(128) __half g_h[(size_t)N_ROWS * D_HID];   // gelu(h) fp16

// ---------------------------------------------------------------------------
// PTX helpers
// ---------------------------------------------------------------------------
__device__ __forceinline__ uint32_t smem_u32(const void* p) {
    uint32_t a;
    asm("{ .reg .u64 t; cvta.to.shared.u64 t, %1; cvt.u32.u64 %0, t; }" : "=r"(a) : "l"(p));
    return a;
}
__device__ __forceinline__ void cp16(uint32_t s, const void* g) {
    asm volatile("cp.async.cg.shared.global [%0], [%1], 16;" :: "r"(s), "l"(g));
}
#define CP_COMMIT() asm volatile("cp.async.commit_group;" ::: "memory")
#define CP_WAIT(n)  asm volatile("cp.async.wait_group %0;" :: "n"(n) : "memory")

#define LDSM4(r0, r1, r2, r3, addr) \
    asm volatile("ldmatrix.sync.aligned.m8n8.x4.shared.b16 {%0,%1,%2,%3}, [%4];" \
                 : "=r"(r0), "=r"(r1), "=r"(r2), "=r"(r3) : "r"(addr))

#define MMA_F16(c, a, b0, b1) \
    asm volatile("mma.sync.aligned.m16n8k16.row.col.f32.f16.f16.f32 " \
                 "{%0,%1,%2,%3},{%4,%5,%6,%7},{%8,%9},{%0,%1,%2,%3};" \
                 : "+f"((c)[0]), "+f"((c)[1]), "+f"((c)[2]), "+f"((c)[3]) \
                 : "r"((a)[0]), "r"((a)[1]), "r"((a)[2]), "r"((a)[3]), "r"(b0), "r"(b1))

// ---------------------------------------------------------------------------
// 1) Gram-Schmidt (batched-CGS) + WY T matrix. Single block, 256 threads.
// ---------------------------------------------------------------------------
#define GS_SMEM ((RANK + 1) * D_IN * 4)     // su[8][2048] + cur[2048] = 73728 B

__global__ void gs_kernel(const float* __restrict__ hra_u,
                          float* __restrict__ u_out, float* __restrict__ Tmat) {
    extern __shared__ float sdyn[];
    float* su  = sdyn;
    float* cur = sdyn + RANK * D_IN;
    __shared__ float swarp[8][8];
    __shared__ float sdots[8];
    __shared__ float sredv[8];
    __shared__ float sG[28];

    const int tid  = threadIdx.x;
    const int lane = tid & 31;
    const int warp = tid >> 5;

    for (int i = 0; i < RANK; i++) {
        #pragma unroll
        for (int e = 0; e < 8; e++) {
            const int d = tid + e * 256;
            cur[d] = hra_u[(size_t)d * RANK + i];
        }
        __syncthreads();

        if (i > 0) {
            float pd[7];
            #pragma unroll
            for (int j = 0; j < 7; j++) pd[j] = 0.f;
            #pragma unroll
            for (int e = 0; e < 8; e++) {
                const int d = tid + e * 256;
                const float c = cur[d];
                #pragma unroll
                for (int j = 0; j < 7; j++)
                    if (j < i) pd[j] += su[j * D_IN + d] * c;
            }
            #pragma unroll
            for (int j = 0; j < 7; j++) {
                #pragma unroll
                for (int o = 16; o > 0; o >>= 1)
                    pd[j] += __shfl_down_sync(0xffffffffu, pd[j], o);
            }
            if (lane == 0) {
                #pragma unroll
                for (int j = 0; j < 7; j++) swarp[warp][j] = pd[j];
            }
            __syncthreads();
            if (tid < 7 && tid < i) {
                float s = 0.f;
                #pragma unroll
                for (int w = 0; w < 8; w++) s += swarp[w][tid];
                sdots[tid] = s;
            }
            __syncthreads();
            #pragma unroll
            for (int e = 0; e < 8; e++) {
                const int d = tid + e * 256;
                float s = 0.f;
                #pragma unroll
                for (int j = 0; j < 7; j++)
                    if (j < i) s += sdots[j] * su[j * D_IN + d];
                cur[d] -= s;
            }
        }

        float nq = 0.f;
        #pragma unroll
        for (int e = 0; e < 8; e++) {
            const int d = tid + e * 256;
            nq += cur[d] * cur[d];
        }
        #pragma unroll
        for (int o = 16; o > 0; o >>= 1) nq += __shfl_down_sync(0xffffffffu, nq, o);
        if (lane == 0) sredv[warp] = nq;
        __syncthreads();
        if (tid == 0) {
            float r = sredv[0];
            #pragma unroll
            for (int w = 1; w < 8; w++) r += sredv[w];
            sredv[0] = 1.0f / (sqrtf(r) + 1e-6f);
        }
        __syncthreads();
        const float inv = sredv[0];
        #pragma unroll
        for (int e = 0; e < 8; e++) {
            const int d = tid + e * 256;
            const float v = cur[d] * inv;
            su[i * D_IN + d] = v;
            u_out[(size_t)i * D_IN + d] = v;
        }
        __syncthreads();
    }

    // Gram pairs + T recurrence
    {
        float pg[28];
        #pragma unroll
        for (int p = 0; p < 28; p++) pg[p] = 0.f;
        #pragma unroll
        for (int e = 0; e < 8; e++) {
            const int d = tid + e * 256;
            float uj[8];
            #pragma unroll
            for (int j = 0; j < 8; j++) uj[j] = su[j * D_IN + d];
            int p = 0;
            #pragma unroll
            for (int k = 1; k < 8; k++)
                #pragma unroll
                for (int j = 0; j < 8; j++)
                    if (j < k) { pg[p] += uj[j] * uj[k]; p++; }
        }
        __shared__ float swg[8][28];
        #pragma unroll
        for (int p = 0; p < 28; p++) {
            #pragma unroll
            for (int o = 16; o > 0; o >>= 1)
                pg[p] += __shfl_down_sync(0xffffffffu, pg[p], o);
        }
        if (lane == 0) {
            #pragma unroll
            for (int p = 0; p < 28; p++) swg[warp][p] = pg[p];
        }
        __syncthreads();
        if (tid < 28) {
            float s = 0.f;
            #pragma unroll
            for (int w = 0; w < 8; w++) s += swg[w][tid];
            sG[tid] = s;
        }
        __syncthreads();
        if (tid == 0) {
            float T[8][8], G[8][8];
            #pragma unroll
            for (int a = 0; a < 8; a++)
                #pragma unroll
                for (int b = 0; b < 8; b++) { T[a][b] = 0.f; G[a][b] = 0.f; }
            int p = 0;
            for (int k = 1; k < 8; k++)
                for (int j = 0; j < k; j++) { G[j][k] = sG[p]; p++; }
            T[0][0] = 2.0f;
            for (int k = 1; k < 8; k++) {
                for (int j = 0; j < k; j++) {
                    float s = 0.f;
                    for (int l = j; l < k; l++) s += T[j][l] * G[l][k];
                    T[j][k] = -2.0f * s;
                }
                T[k][k] = 2.0f;
            }
            for (int a = 0; a < 8; a++)
                for (int b = 0; b < 8; b++) Tmat[a * 8 + b] = T[a][b];
        }
    }
}

// ---------------------------------------------------------------------------
// 2) x @ Q via WY form: v = x - ((xU) T) U^T.
// ---------------------------------------------------------------------------
__global__ void __launch_bounds__(256) hh_kernel(const float* __restrict__ x,
                                                 const float* __restrict__ u,
                                                 const float* __restrict__ Tmat,
                                                 __half* __restrict__ xq) {
    __shared__ float swarp[8][8];
    __shared__ float sdots[8];
    __shared__ float sT[64];
    __shared__ float sq[8];
    const int row  = blockIdx.x;
    const int tid  = threadIdx.x;
    const int lane = tid & 31;
    const int warp = tid >> 5;
    const float* xr = x + (size_t)row * D_IN;

    if (tid < 64) sT[tid] = Tmat[tid];

    float v[8];
    #pragma unroll
    for (int e = 0; e < 8; e++) v[e] = xr[tid + e * 256];

    float pd[8];
    #pragma unroll
    for (int j = 0; j < 8; j++) pd[j] = 0.f;
    #pragma unroll
    for (int e = 0; e < 8; e++) {
        const int d = tid + e * 256;
        const float c = v[e];
        #pragma unroll
        for (int j = 0; j < 8; j++) pd[j] += u[(size_t)j * D_IN + d] * c;
    }
    #pragma unroll
    for (int j = 0; j < 8; j++) {
        #pragma unroll
        for (int o = 16; o > 0; o >>= 1)
            pd[j] += __shfl_down_sync(0xffffffffu, pd[j], o);
    }
    if (lane == 0) {
        #pragma unroll
        for (int j = 0; j < 8; j++) swarp[warp][j] = pd[j];
    }
    __syncthreads();
    if (tid < 8) {
        float s = 0.f;
        #pragma unroll
        for (int w = 0; w < 8; w++) s += swarp[w][tid];
        sdots[tid] = s;
    }
    __syncthreads();
    if (tid < 8) {
        float s = 0.f;
        #pragma unroll
        for (int i = 0; i < 8; i++) s += sdots[i] * sT[i * 8 + tid];
        sq[tid] = s;
    }
    __syncthreads();

    float q[8];
    #pragma unroll
    for (int j = 0; j < 8; j++) q[j] = sq[j];

    #pragma unroll
    for (int e = 0; e < 8; e++) {
        const int d = tid + e * 256;
        float s = 0.f;
        #pragma unroll
        for (int j = 0; j < 8; j++) s += q[j] * u[(size_t)j * D_IN + d];
        xq[(size_t)row * D_IN + d] = __float2half_rn(v[e] - s);
    }
}

// ---------------------------------------------------------------------------
// 3) Transpose to fp16: in[R,C] fp32 -> out[C,R] fp16
// ---------------------------------------------------------------------------
__global__ void __launch_bounds__(256) transpose_half_kernel(
    const float* __restrict__ in, __half* __restrict__ outp, int R, int C) {
    __shared__ float tile[32][33];
    const int c0 = blockIdx.x * 32, r0 = blockIdx.y * 32;
    const int tx = threadIdx.x, ty = threadIdx.y;
    #pragma unroll
    for (int j = 0; j < 32; j += 8)
        tile[ty + j][tx] = in[(size_t)(r0 + ty + j) * C + c0 + tx];
    __syncthreads();
    #pragma unroll
    for (int j = 0; j < 32; j += 8) {
        float v = tile[tx][ty + j];
        outp[(size_t)(c0 + ty + j) * R + r0 + tx] = __float2half_rn(v);
    }
}

// ---------------------------------------------------------------------------
// 4) HMMA GEMM: C[M,N] = A[M,K] * B[N,K]^T, fp16, fp32 accum.
//    Block 64x128, BK=128, 8 warps (2 M x 4 N), warp tile 32x32.
//    2-stage cp.async (CP_WAIT(0)), 2 CTAs/SM, SW128 swizzle on 256B rows,
//    register double-buffered ldmatrix fragments.
// ---------------------------------------------------------------------------
#define BM 64
#define BN 128
#define BK 128
#define ROW_B 256                               // 128 fp16 = 256 B per row
#define A_TILE_B (BM * ROW_B)                   // 16384
#define B_TILE_B (BN * ROW_B)                   // 32768
#define STAGE_BYTES (A_TILE_B + B_TILE_B)       // 49152
#define GEMM_SMEM (2 * STAGE_BYTES)             // 98304 -> 2 CTAs/SM

__device__ __forceinline__ void load_stage(uint32_t sb,
                                           const __half* __restrict__ A,
                                           const __half* __restrict__ B,
                                           int m0, int n0, int kc, int K, int tid) {
    // A: 64 rows x 16 chunks = 1024 ; B: 128 rows x 16 chunks = 2048
    #pragma unroll
    for (int i = 0; i < 4; i++) {
        const int id = tid + i * 256;
        const int r = id >> 4;                  // 0..63
        const int c = id & 15;                  // 16B chunk 0..15
        const uint32_t so = (uint32_t)(r * ROW_B) + (((uint32_t)(c ^ (r & 7))) << 4);
        cp16(sb + so, A + (size_t)(m0 + r) * K + kc + c * 8);
    }
    #pragma unroll
    for (int i = 0; i < 8; i++) {
        const int id = tid + i * 256;
        const int r = id >> 4;                  // 0..127
        const int c = id & 15;
        const uint32_t so = (uint32_t)(r * ROW_B) + (((uint32_t)(c ^ (r & 7))) << 4);
        cp16(sb + A_TILE_B + so, B + (size_t)(n0 + r) * K + kc + c * 8);
    }
}

template<int EPI>
__global__ void __launch_bounds__(256, 2) gemm_hmma_f16(
    const __half* __restrict__ A, const __half* __restrict__ B,
    float* __restrict__ Cf, __half* __restrict__ Ch,
    const float* __restrict__ bias, int K, int ldc) {
    extern __shared__ char smem[];
    const uint32_t sb = smem_u32(smem);
    const int tid = threadIdx.x;
    const int lane = tid & 31;
    const int wid = tid >> 5;
    const int wm = wid & 1;           // 2 warps along M (32 rows each)
    const int wn = wid >> 1;          // 4 warps along N (32 cols each)
    const int m0 = blockIdx.y * BM;
    const int n0 = blockIdx.x * BN;

    float acc[2][4][4];               // [mt][nt][frag]
    #pragma unroll
    for (int i = 0; i < 2; i++)
        #pragma unroll
        for (int j = 0; j < 4; j++)
            #pragma unroll
            for (int q = 0; q < 4; q++) acc[i][j][q] = 0.f;

    const int NT = K / BK;

    load_stage(sb, A, B, m0, n0, 0, K, tid);
    CP_COMMIT();

    const int rowA  = wm * 32 + (lane & 15);
    const uint32_t partA = ((uint32_t)(lane >> 4)) << 4;
    const uint32_t xorA  = ((uint32_t)(rowA & 7)) << 4;
    const int rowB  = wn * 32 + (lane & 7) + ((lane >> 4) << 3);
    const uint32_t partB = ((uint32_t)((lane >> 3) & 1)) << 4;
    const uint32_t xorB  = ((uint32_t)(rowB & 7)) << 4;

    uint32_t af[2][2][4], bf[2][2][4];

#define LOAD_FRAGS(buf, kk, st_) do { \
    const uint32_t cbA = (((uint32_t)(kk) * 32) + partA) ^ xorA; \
    const uint32_t cbB = (((uint32_t)(kk) * 32) + partB) ^ xorB; \
    _Pragma("unroll") \
    for (int mt = 0; mt < 2; mt++) { \
        const uint32_t aa = (st_) + (uint32_t)((rowA + mt * 16) * ROW_B) + cbA; \
        LDSM4(af[buf][mt][0], af[buf][mt][1], af[buf][mt][2], af[buf][mt][3], aa); \
    } \
    _Pragma("unroll") \
    for (int np = 0; np < 2; np++) { \
        const uint32_t ba = (st_) + A_TILE_B + (uint32_t)((rowB + np * 16) * ROW_B) + cbB; \
        LDSM4(bf[buf][np][0], bf[buf][np][1], bf[buf][np][2], bf[buf][np][3], ba); \
    } \
} while (0)

    for (int t = 0; t < NT; t++) {
        CP_WAIT(0);                    // stage t resident
        __syncthreads();               // all warps done reading slot (t-1)&1

        if (t + 1 < NT)
            load_stage(sb + ((t + 1) & 1) * STAGE_BYTES,
                       A, B, m0, n0, (t + 1) * BK, K, tid);
        CP_COMMIT();

        const uint32_t st = sb + (t & 1) * STAGE_BYTES;
        LOAD_FRAGS(0, 0, st);
        #pragma unroll
        for (int kk = 0; kk < 8; kk++) {
            const int cb = kk & 1;
            if (kk < 7) LOAD_FRAGS(cb ^ 1, kk + 1, st);
            #pragma unroll
            for (int mt = 0; mt < 2; mt++) {
                #pragma unroll
                for (int np = 0; np < 2; np++) {
                    MMA_F16(acc[mt][2 * np],     af[cb][mt], bf[cb][np][0], bf[cb][np][1]);
                    MMA_F16(acc[mt][2 * np + 1], af[cb][mt], bf[cb][np][2], bf[cb][np][3]);
                }
            }
        }
    }
#undef LOAD_FRAGS

    // ---- epilogue
    #pragma unroll
    for (int mt = 0; mt < 2; mt++) {
        const int r0 = m0 + wm * 32 + mt * 16 + (lane >> 2);
        #pragma unroll
        for (int nt = 0; nt < 4; nt++) {
            const int col = n0 + wn * 32 + nt * 8 + (lane & 3) * 2;
            const float* a4 = acc[mt][nt];
            if (EPI == 0) {
                #pragma unroll
                for (int h = 0; h < 2; h++) {
                    const int rr = r0 + h * 8;
                    float v0 = a4[2 * h + 0], v1 = a4[2 * h + 1];
                    v0 = 0.5f * v0 * (1.0f + erff(v0 * 0.70710678118654752f));
                    v1 = 0.5f * v1 * (1.0f + erff(v1 * 0.70710678118654752f));
                    uint32_t ph = (uint32_t)__half_as_ushort(__float2half_rn(v0)) |
                                  ((uint32_t)__half_as_ushort(__float2half_rn(v1)) << 16);
                    *(uint32_t*)(Ch + (size_t)rr * ldc + col) = ph;
                }
            } else {
                const float b0 = __ldg(bias + col);
                const float b1 = __ldg(bias + col + 1);
                #pragma unroll
                for (int h = 0; h < 2; h++) {
                    const int rr = r0 + h * 8;
                    float2 v;
                    v.x = a4[2 * h + 0] + b0;
                    v.y = a4[2 * h + 1] + b1;
                    *(float2*)(Cf + (size_t)rr * ldc + col) = v;
                }
            }
        }
    }
}

// ---------------------------------------------------------------------------
// Launcher. Order: transpose(Wr), gs, hh, GEMM1, transpose(Wo), GEMM2
// ---------------------------------------------------------------------------
extern "C" void kernel_launch(void* const* d_in, const int* in_sizes, int n_in,
                              void* d_out, int out_size) {
    const float* x        = (const float*)d_in[0];
    const float* hra_u    = (const float*)d_in[1];
    const float* W_random = (const float*)d_in[2];
    const float* W_out    = (const float*)d_in[3];
    const float* bias     = (const float*)d_in[4];
    float*       out      = (float*)d_out;

    float *u_p, *T_p; __half *xq, *wt, *wo, *hp;
    cudaGetSymbolAddress((void**)&u_p, g_u);
    cudaGetSymbolAddress((void**)&T_p, g_T);
    cudaGetSymbolAddress((void**)&xq,  g_xq);
    cudaGetSymbolAddress((void**)&wt,  g_wt);
    cudaGetSymbolAddress((void**)&wo,  g_wo);
    cudaGetSymbolAddress((void**)&hp,  g_h);

    cudaFuncSetAttribute(gs_kernel, cudaFuncAttributeMaxDynamicSharedMemorySize, GS_SMEM);
    cudaFuncSetAttribute(gemm_hmma_f16<0>, cudaFuncAttributeMaxDynamicSharedMemorySize, GEMM_SMEM);
    cudaFuncSetAttribute(gemm_hmma_f16<1>, cudaFuncAttributeMaxDynamicSharedMemorySize, GEMM_SMEM);

    transpose_half_kernel<<<dim3(D_HID / 32, D_IN / 32), dim3(32, 8)>>>(W_random, wt, D_IN, D_HID);
    gs_kernel<<<1, 256, GS_SMEM>>>(hra_u, u_p, T_p);
    hh_kernel<<<N_ROWS, 256>>>(x, u_p, T_p, xq);

    // GEMM1: h = gelu(xq @ Wt^T)   M=4096, N=8192, K=2048
    gemm_hmma_f16<0><<<dim3(D_HID / BN, N_ROWS / BM), 256, GEMM_SMEM>>>(
        xq, wt, nullptr, hp, nullptr, D_IN, D_HID);

    transpose_half_kernel<<<dim3(D_OUT / 32, D_HID / 32), dim3(32, 8)>>>(W_out, wo, D_HID, D_OUT);

    // GEMM2: out = h @ Wo^T + bias   M=4096, N=2048, K=8192
    gemm_hmma_f16<1><<<dim3(D_OUT / BN, N_ROWS / BM), 256, GEMM_SMEM>>>(
        hp, wo, out, nullptr, bias, D_HID, D_OUT);
}